// round 2
// baseline (speedup 1.0000x reference)
#include <cuda_runtime.h>
#include <cuda_bf16.h>

#define N_NODES  100000
#define N_EDGES  1600000
#define HID      128
#define LAT      64
#define N_LAYERS 3
#define N_GRAPHS 1000

// Scratch (allocation-free rule: __device__ globals)
__device__ float g_agg[(size_t)N_NODES * HID];
__device__ float g_h[(size_t)N_NODES * HID];
__device__ float g_pool[(size_t)N_GRAPHS * HID];

// ---------------------------------------------------------------------------
// agg = src (vector copy into g_agg)
// ---------------------------------------------------------------------------
__global__ void __launch_bounds__(256) copy_init(const float* __restrict__ src) {
    int i = blockIdx.x * 256 + threadIdx.x;            // N_NODES*HID/4 = 3.2M threads exact
    float4 v = ((const float4*)src)[i];
    ((float4*)g_agg)[i] = v;
}

// ---------------------------------------------------------------------------
// scatter: g_agg[dst] += h[src] over all edges.
// One thread per (edge, 4-float chunk); 32 consecutive threads share an edge
// -> coalesced 512B gather per warp, src/dst broadcast via L1.
// ---------------------------------------------------------------------------
__global__ void __launch_bounds__(256) scatter_add(
    const float* __restrict__ h,
    const int* __restrict__ src,
    const int* __restrict__ dst)
{
    int idx = blockIdx.x * 256 + threadIdx.x;          // N_EDGES*32 = 51.2M exact
    int e = idx >> 5;
    int c = idx & 31;
    int s = src[e];
    int d = dst[e];
    float4 v = ((const float4*)(h + (size_t)s * HID))[c];
    float* p = g_agg + (size_t)d * HID + c * 4;
    atomicAdd(p + 0, v.x);
    atomicAdd(p + 1, v.y);
    atomicAdd(p + 2, v.z);
    atomicAdd(p + 3, v.w);
}

// ---------------------------------------------------------------------------
// Fused 2-layer MLP: out = relu(relu(in@W1 + b1)@W2 + b2)
// 64-row tiles, W1+W2+tile all in SMEM (192KB), 8x4 register blocking.
// ---------------------------------------------------------------------------
__global__ void __launch_bounds__(256) mlp2(
    const float* __restrict__ in,
    const float* __restrict__ W1g, const float* __restrict__ b1g,
    const float* __restrict__ W2g, const float* __restrict__ b2g,
    float* __restrict__ out, int nrows)
{
    extern __shared__ float s[];
    float* sW1  = s;                 // 16384 floats
    float* sW2  = s + 16384;         // 16384 floats
    float* sIn  = s + 32768;         // 8192  floats (64 x 128)
    float* sMid = s + 40960;         // 8192  floats

    const int tid = threadIdx.x;

    // stage weights
    {
        const float4* W14 = (const float4*)W1g;
        const float4* W24 = (const float4*)W2g;
        float4* sW14 = (float4*)sW1;
        float4* sW24 = (float4*)sW2;
        #pragma unroll 4
        for (int i = tid; i < 4096; i += 256) { sW14[i] = W14[i]; sW24[i] = W24[i]; }
    }

    const int row0 = blockIdx.x * 64;

    // stage input tile (zero-pad past nrows)
    {
        float4* sIn4 = (float4*)sIn;
        #pragma unroll 2
        for (int i = tid; i < 64 * 32; i += 256) {
            int r = i >> 5;
            int gr = row0 + r;
            float4 v = make_float4(0.f, 0.f, 0.f, 0.f);
            if (gr < nrows) v = ((const float4*)(in + (size_t)gr * HID))[i & 31];
            sIn4[i] = v;
        }
    }
    __syncthreads();

    const int cg = tid & 31;   // 4 output cols: 4*cg..4*cg+3
    const int rg = tid >> 5;   // 8 rows: rg*8..rg*8+7  (whole warp shares rg -> sIn broadcast)

    float acc[8][4];

    // ---- GEMM1: mid = relu(in @ W1 + b1) ----
    {
        float4 bv = ((const float4*)b1g)[cg];
        #pragma unroll
        for (int j = 0; j < 8; j++) { acc[j][0]=bv.x; acc[j][1]=bv.y; acc[j][2]=bv.z; acc[j][3]=bv.w; }

        const float4* sW14 = (const float4*)sW1;
        #pragma unroll 4
        for (int k = 0; k < HID; k++) {
            float4 w = sW14[k * 32 + cg];
            #pragma unroll
            for (int j = 0; j < 8; j++) {
                float a = sIn[(rg * 8 + j) * HID + k];
                acc[j][0] += a * w.x; acc[j][1] += a * w.y;
                acc[j][2] += a * w.z; acc[j][3] += a * w.w;
            }
        }
        #pragma unroll
        for (int j = 0; j < 8; j++) {
            float4 v;
            v.x = fmaxf(acc[j][0], 0.f); v.y = fmaxf(acc[j][1], 0.f);
            v.z = fmaxf(acc[j][2], 0.f); v.w = fmaxf(acc[j][3], 0.f);
            ((float4*)(sMid + (rg * 8 + j) * HID))[cg] = v;
        }
    }
    __syncthreads();

    // ---- GEMM2: out = relu(mid @ W2 + b2) ----
    {
        float4 bv = ((const float4*)b2g)[cg];
        #pragma unroll
        for (int j = 0; j < 8; j++) { acc[j][0]=bv.x; acc[j][1]=bv.y; acc[j][2]=bv.z; acc[j][3]=bv.w; }

        const float4* sW24 = (const float4*)sW2;
        #pragma unroll 4
        for (int k = 0; k < HID; k++) {
            float4 w = sW24[k * 32 + cg];
            #pragma unroll
            for (int j = 0; j < 8; j++) {
                float a = sMid[(rg * 8 + j) * HID + k];
                acc[j][0] += a * w.x; acc[j][1] += a * w.y;
                acc[j][2] += a * w.z; acc[j][3] += a * w.w;
            }
        }
        #pragma unroll
        for (int j = 0; j < 8; j++) {
            int gr = row0 + rg * 8 + j;
            if (gr < nrows) {
                float4 v;
                v.x = fmaxf(acc[j][0], 0.f); v.y = fmaxf(acc[j][1], 0.f);
                v.z = fmaxf(acc[j][2], 0.f); v.w = fmaxf(acc[j][3], 0.f);
                ((float4*)(out + (size_t)gr * HID))[cg] = v;
            }
        }
    }
}

// ---------------------------------------------------------------------------
// zero the pool accumulator
// ---------------------------------------------------------------------------
__global__ void __launch_bounds__(256) zero_pool() {
    int i = blockIdx.x * 256 + threadIdx.x;            // N_GRAPHS*HID = 128000, 500 blocks exact
    g_pool[i] = 0.f;
}

// ---------------------------------------------------------------------------
// pool: g_pool[batch[n]] += h[n]. batch is sorted -> accumulate in registers,
// emit an atomic only on segment boundaries. 128 threads = 1 col each.
// ---------------------------------------------------------------------------
__global__ void __launch_bounds__(128) pool_sum(
    const float* __restrict__ h, const int* __restrict__ batch)
{
    const int CHUNK = 256;
    int col = threadIdx.x;
    int n0 = blockIdx.x * CHUNK;
    int n1 = n0 + CHUNK; if (n1 > N_NODES) n1 = N_NODES;
    if (n0 >= N_NODES) return;

    int cur = batch[n0];
    float acc = 0.f;
    for (int n = n0; n < n1; n++) {
        int b = batch[n];
        if (b != cur) {
            atomicAdd(&g_pool[(size_t)cur * HID + col], acc);
            acc = 0.f;
            cur = b;
        }
        acc += h[(size_t)n * HID + col];
    }
    atomicAdd(&g_pool[(size_t)cur * HID + col], acc);
}

// ---------------------------------------------------------------------------
// heads: mu = g@W_mu + b_mu ; logvar = g@W_lv + b_lv
// one block per graph; threads 0..63 -> mu, 64..127 -> logvar
// ---------------------------------------------------------------------------
__global__ void __launch_bounds__(128) heads(
    const float* __restrict__ Wmu, const float* __restrict__ bmu,
    const float* __restrict__ Wlv, const float* __restrict__ blv,
    float* __restrict__ out)
{
    __shared__ float sg[HID];
    int gi = blockIdx.x;
    sg[threadIdx.x] = g_pool[(size_t)gi * HID + threadIdx.x];
    __syncthreads();

    int t = threadIdx.x;
    const float* W = (t < LAT) ? Wmu : Wlv;
    const float* b = (t < LAT) ? bmu : blv;
    int c = t & (LAT - 1);
    float acc = b[c];
    #pragma unroll 8
    for (int k = 0; k < HID; k++) acc += sg[k] * W[k * LAT + c];

    float* o = (t < LAT) ? out : (out + (size_t)N_GRAPHS * LAT);
    o[(size_t)gi * LAT + c] = acc;
}

// ---------------------------------------------------------------------------

extern "C" void kernel_launch(void* const* d_in, const int* in_sizes, int n_in,
                              void* d_out, int out_size) {
    const float* x     = (const float*)d_in[0];
    const int*   ei    = (const int*)d_in[1];   // [2, N_EDGES] int32 (JAX x64 disabled)
    const int*   batch = (const int*)d_in[2];   // [N_NODES] int32, sorted
    const float* W1    = (const float*)d_in[3]; // [3,128,128]
    const float* b1    = (const float*)d_in[4]; // [3,128]
    const float* W2    = (const float*)d_in[5];
    const float* b2    = (const float*)d_in[6];
    const float* Wmu   = (const float*)d_in[7]; // [128,64]
    const float* bmu   = (const float*)d_in[8];
    const float* Wlv   = (const float*)d_in[9];
    const float* blv   = (const float*)d_in[10];
    float*       out   = (float*)d_out;

    cudaFuncSetAttribute(mlp2, cudaFuncAttributeMaxDynamicSharedMemorySize, 196608);

    const int* src = ei;
    const int* dst = ei + N_EDGES;

    float* h_ptr;   cudaGetSymbolAddress((void**)&h_ptr, g_h);
    float* agg_ptr; cudaGetSymbolAddress((void**)&agg_ptr, g_agg);

    const int MLP_BLOCKS = (N_NODES + 63) / 64;          // 1563

    const float* cur = x;
    for (int l = 0; l < N_LAYERS; l++) {
        copy_init<<<(N_NODES * HID / 4) / 256, 256>>>(cur);                 // g_agg = cur
        scatter_add<<<(N_EDGES * 32) / 256, 256>>>(cur, src, dst);          // g_agg += scatter
        mlp2<<<MLP_BLOCKS, 256, 196608>>>(agg_ptr,
                                          W1 + (size_t)l * HID * HID, b1 + (size_t)l * HID,
                                          W2 + (size_t)l * HID * HID, b2 + (size_t)l * HID,
                                          h_ptr, N_NODES);
        cur = h_ptr;
    }

    zero_pool<<<(N_GRAPHS * HID) / 256, 256>>>();
    pool_sum<<<(N_NODES + 255) / 256, 128>>>(cur, batch);
    heads<<<N_GRAPHS, 128>>>(Wmu, bmu, Wlv, blv, out);
}

// round 3
// speedup vs baseline: 1.5917x; 1.5917x over previous
#include <cuda_runtime.h>
#include <cuda_bf16.h>

#define N_NODES  100000
#define N_EDGES  1600000
#define HID      128
#define LAT      64
#define N_LAYERS 3
#define N_GRAPHS 1000

// Scratch (allocation-free rule: __device__ globals). 128B-aligned so float4
// chunks are 16B-aligned for vector reductions.
__device__ __align__(128) float g_agg[(size_t)N_NODES * HID];
__device__ __align__(128) float g_h[(size_t)N_NODES * HID];
__device__ __align__(128) float g_pool[(size_t)N_GRAPHS * HID];

// ---------------------------------------------------------------------------
// agg = src (vector copy into g_agg)
// ---------------------------------------------------------------------------
__global__ void __launch_bounds__(256) copy_init(const float* __restrict__ src) {
    int i = blockIdx.x * 256 + threadIdx.x;            // N_NODES*HID/4 = 3.2M threads exact
    float4 v = ((const float4*)src)[i];
    ((float4*)g_agg)[i] = v;
}

// ---------------------------------------------------------------------------
// scatter: g_agg[dst] += h[src] over all edges.
// One thread per (edge, 4-float chunk); 32 consecutive threads share an edge
// -> coalesced 512B gather per warp. One vectorized L2 reduction per thread
// (red.global.v4.f32.add) instead of 4 scalar atomics: 4x fewer LTS atomic ops.
// ---------------------------------------------------------------------------
__global__ void __launch_bounds__(256) scatter_add(
    const float* __restrict__ h,
    const int* __restrict__ src,
    const int* __restrict__ dst)
{
    int idx = blockIdx.x * 256 + threadIdx.x;          // N_EDGES*32 = 51.2M exact
    int e = idx >> 5;
    int c = idx & 31;
    int s = src[e];
    int d = dst[e];
    float4 v = ((const float4*)(h + (size_t)s * HID))[c];
    float* p = g_agg + (size_t)d * HID + (size_t)c * 4;
    asm volatile("red.global.v4.f32.add [%0], {%1, %2, %3, %4};"
                 :: "l"(p), "f"(v.x), "f"(v.y), "f"(v.z), "f"(v.w)
                 : "memory");
}

// ---------------------------------------------------------------------------
// Fused 2-layer MLP: out = relu(relu(in@W1 + b1)@W2 + b2)
// 64-row tiles, W1+W2+tile all in SMEM (192KB), 8x4 register blocking.
// (FMA-pipe-bound at ~580us total; tensor-core rewrite is the next lever.)
// ---------------------------------------------------------------------------
__global__ void __launch_bounds__(256) mlp2(
    const float* __restrict__ in,
    const float* __restrict__ W1g, const float* __restrict__ b1g,
    const float* __restrict__ W2g, const float* __restrict__ b2g,
    float* __restrict__ out, int nrows)
{
    extern __shared__ float s[];
    float* sW1  = s;                 // 16384 floats
    float* sW2  = s + 16384;         // 16384 floats
    float* sIn  = s + 32768;         // 8192  floats (64 x 128)
    float* sMid = s + 40960;         // 8192  floats

    const int tid = threadIdx.x;

    // stage weights
    {
        const float4* W14 = (const float4*)W1g;
        const float4* W24 = (const float4*)W2g;
        float4* sW14 = (float4*)sW1;
        float4* sW24 = (float4*)sW2;
        #pragma unroll 4
        for (int i = tid; i < 4096; i += 256) { sW14[i] = W14[i]; sW24[i] = W24[i]; }
    }

    const int row0 = blockIdx.x * 64;

    // stage input tile (zero-pad past nrows)
    {
        float4* sIn4 = (float4*)sIn;
        #pragma unroll 2
        for (int i = tid; i < 64 * 32; i += 256) {
            int r = i >> 5;
            int gr = row0 + r;
            float4 v = make_float4(0.f, 0.f, 0.f, 0.f);
            if (gr < nrows) v = ((const float4*)(in + (size_t)gr * HID))[i & 31];
            sIn4[i] = v;
        }
    }
    __syncthreads();

    const int cg = tid & 31;   // 4 output cols: 4*cg..4*cg+3
    const int rg = tid >> 5;   // 8 rows: rg*8..rg*8+7  (whole warp shares rg -> sIn broadcast)

    float acc[8][4];

    // ---- GEMM1: mid = relu(in @ W1 + b1) ----
    {
        float4 bv = ((const float4*)b1g)[cg];
        #pragma unroll
        for (int j = 0; j < 8; j++) { acc[j][0]=bv.x; acc[j][1]=bv.y; acc[j][2]=bv.z; acc[j][3]=bv.w; }

        const float4* sW14 = (const float4*)sW1;
        #pragma unroll 4
        for (int k = 0; k < HID; k++) {
            float4 w = sW14[k * 32 + cg];
            #pragma unroll
            for (int j = 0; j < 8; j++) {
                float a = sIn[(rg * 8 + j) * HID + k];
                acc[j][0] += a * w.x; acc[j][1] += a * w.y;
                acc[j][2] += a * w.z; acc[j][3] += a * w.w;
            }
        }
        #pragma unroll
        for (int j = 0; j < 8; j++) {
            float4 v;
            v.x = fmaxf(acc[j][0], 0.f); v.y = fmaxf(acc[j][1], 0.f);
            v.z = fmaxf(acc[j][2], 0.f); v.w = fmaxf(acc[j][3], 0.f);
            ((float4*)(sMid + (rg * 8 + j) * HID))[cg] = v;
        }
    }
    __syncthreads();

    // ---- GEMM2: out = relu(mid @ W2 + b2) ----
    {
        float4 bv = ((const float4*)b2g)[cg];
        #pragma unroll
        for (int j = 0; j < 8; j++) { acc[j][0]=bv.x; acc[j][1]=bv.y; acc[j][2]=bv.z; acc[j][3]=bv.w; }

        const float4* sW24 = (const float4*)sW2;
        #pragma unroll 4
        for (int k = 0; k < HID; k++) {
            float4 w = sW24[k * 32 + cg];
            #pragma unroll
            for (int j = 0; j < 8; j++) {
                float a = sMid[(rg * 8 + j) * HID + k];
                acc[j][0] += a * w.x; acc[j][1] += a * w.y;
                acc[j][2] += a * w.z; acc[j][3] += a * w.w;
            }
        }
        #pragma unroll
        for (int j = 0; j < 8; j++) {
            int gr = row0 + rg * 8 + j;
            if (gr < nrows) {
                float4 v;
                v.x = fmaxf(acc[j][0], 0.f); v.y = fmaxf(acc[j][1], 0.f);
                v.z = fmaxf(acc[j][2], 0.f); v.w = fmaxf(acc[j][3], 0.f);
                ((float4*)(out + (size_t)gr * HID))[cg] = v;
            }
        }
    }
}

// ---------------------------------------------------------------------------
// zero the pool accumulator
// ---------------------------------------------------------------------------
__global__ void __launch_bounds__(256) zero_pool() {
    int i = blockIdx.x * 256 + threadIdx.x;            // N_GRAPHS*HID = 128000, 500 blocks exact
    g_pool[i] = 0.f;
}

// ---------------------------------------------------------------------------
// pool: g_pool[batch[n]] += h[n]. batch is sorted -> accumulate in registers,
// emit an atomic only on segment boundaries. 128 threads = 1 col each.
// ---------------------------------------------------------------------------
__global__ void __launch_bounds__(128) pool_sum(
    const float* __restrict__ h, const int* __restrict__ batch)
{
    const int CHUNK = 256;
    int col = threadIdx.x;
    int n0 = blockIdx.x * CHUNK;
    int n1 = n0 + CHUNK; if (n1 > N_NODES) n1 = N_NODES;
    if (n0 >= N_NODES) return;

    int cur = batch[n0];
    float acc = 0.f;
    for (int n = n0; n < n1; n++) {
        int b = batch[n];
        if (b != cur) {
            atomicAdd(&g_pool[(size_t)cur * HID + col], acc);
            acc = 0.f;
            cur = b;
        }
        acc += h[(size_t)n * HID + col];
    }
    atomicAdd(&g_pool[(size_t)cur * HID + col], acc);
}

// ---------------------------------------------------------------------------
// heads: mu = g@W_mu + b_mu ; logvar = g@W_lv + b_lv
// one block per graph; threads 0..63 -> mu, 64..127 -> logvar
// ---------------------------------------------------------------------------
__global__ void __launch_bounds__(128) heads(
    const float* __restrict__ Wmu, const float* __restrict__ bmu,
    const float* __restrict__ Wlv, const float* __restrict__ blv,
    float* __restrict__ out)
{
    __shared__ float sg[HID];
    int gi = blockIdx.x;
    sg[threadIdx.x] = g_pool[(size_t)gi * HID + threadIdx.x];
    __syncthreads();

    int t = threadIdx.x;
    const float* W = (t < LAT) ? Wmu : Wlv;
    const float* b = (t < LAT) ? bmu : blv;
    int c = t & (LAT - 1);
    float acc = b[c];
    #pragma unroll 8
    for (int k = 0; k < HID; k++) acc += sg[k] * W[k * LAT + c];

    float* o = (t < LAT) ? out : (out + (size_t)N_GRAPHS * LAT);
    o[(size_t)gi * LAT + c] = acc;
}

// ---------------------------------------------------------------------------

extern "C" void kernel_launch(void* const* d_in, const int* in_sizes, int n_in,
                              void* d_out, int out_size) {
    const float* x     = (const float*)d_in[0];
    const int*   ei    = (const int*)d_in[1];   // [2, N_EDGES] int32 (JAX x64 disabled)
    const int*   batch = (const int*)d_in[2];   // [N_NODES] int32, sorted
    const float* W1    = (const float*)d_in[3]; // [3,128,128]
    const float* b1    = (const float*)d_in[4]; // [3,128]
    const float* W2    = (const float*)d_in[5];
    const float* b2    = (const float*)d_in[6];
    const float* Wmu   = (const float*)d_in[7]; // [128,64]
    const float* bmu   = (const float*)d_in[8];
    const float* Wlv   = (const float*)d_in[9];
    const float* blv   = (const float*)d_in[10];
    float*       out   = (float*)d_out;

    cudaFuncSetAttribute(mlp2, cudaFuncAttributeMaxDynamicSharedMemorySize, 196608);

    const int* src = ei;
    const int* dst = ei + N_EDGES;

    float* h_ptr;   cudaGetSymbolAddress((void**)&h_ptr, g_h);
    float* agg_ptr; cudaGetSymbolAddress((void**)&agg_ptr, g_agg);

    const int MLP_BLOCKS = (N_NODES + 63) / 64;          // 1563

    const float* cur = x;
    for (int l = 0; l < N_LAYERS; l++) {
        copy_init<<<(N_NODES * HID / 4) / 256, 256>>>(cur);                 // g_agg = cur
        scatter_add<<<(N_EDGES * 32) / 256, 256>>>(cur, src, dst);          // g_agg += scatter
        mlp2<<<MLP_BLOCKS, 256, 196608>>>(agg_ptr,
                                          W1 + (size_t)l * HID * HID, b1 + (size_t)l * HID,
                                          W2 + (size_t)l * HID * HID, b2 + (size_t)l * HID,
                                          h_ptr, N_NODES);
        cur = h_ptr;
    }

    zero_pool<<<(N_GRAPHS * HID) / 256, 256>>>();
    pool_sum<<<(N_NODES + 255) / 256, 128>>>(cur, batch);
    heads<<<N_GRAPHS, 128>>>(Wmu, bmu, Wlv, blv, out);
}

// round 4
// speedup vs baseline: 2.3369x; 1.4681x over previous
#include <cuda_runtime.h>
#include <cuda_bf16.h>

#define N_NODES  100000
#define N_EDGES  1600000
#define HID      128
#define LAT      64
#define N_LAYERS 3
#define N_GRAPHS 1000

#define SCAN_BLK 512
#define SCAN_NB  ((N_NODES + SCAN_BLK - 1) / SCAN_BLK)   // 196

// Scratch (allocation-free rule: __device__ globals)
__device__ __align__(128) float g_agg[(size_t)N_NODES * HID];
__device__ __align__(128) float g_h[(size_t)N_NODES * HID];
__device__ __align__(128) float g_pool[(size_t)N_GRAPHS * HID];
// CSR build scratch
__device__ int g_deg[N_NODES];
__device__ int g_cur[N_NODES];
__device__ int g_off[N_NODES + 1];
__device__ int g_col[N_EDGES];
__device__ int g_part[SCAN_NB];

// ---------------------------------------------------------------------------
// CSR build: histogram -> 2-level exclusive scan -> placement
// ---------------------------------------------------------------------------
__global__ void __launch_bounds__(256) csr_zero() {
    int i = blockIdx.x * 256 + threadIdx.x;
    if (i < N_NODES) { g_deg[i] = 0; g_cur[i] = 0; }
}

__global__ void __launch_bounds__(256) csr_hist(const int* __restrict__ dst) {
    int e = blockIdx.x * 256 + threadIdx.x;              // N_EDGES exact (6250 blocks)
    atomicAdd(&g_deg[dst[e]], 1);
}

__global__ void __launch_bounds__(SCAN_BLK) scan_partial() {
    __shared__ int sm[SCAN_BLK];
    int i = blockIdx.x * SCAN_BLK + threadIdx.x;
    sm[threadIdx.x] = (i < N_NODES) ? g_deg[i] : 0;
    __syncthreads();
    for (int st = SCAN_BLK / 2; st > 0; st >>= 1) {
        if (threadIdx.x < st) sm[threadIdx.x] += sm[threadIdx.x + st];
        __syncthreads();
    }
    if (threadIdx.x == 0) g_part[blockIdx.x] = sm[0];
}

__global__ void __launch_bounds__(32) scan_single() {
    if (threadIdx.x == 0) {
        int acc = 0;
        for (int b = 0; b < SCAN_NB; b++) { int v = g_part[b]; g_part[b] = acc; acc += v; }
        g_off[N_NODES] = N_EDGES;
    }
}

__global__ void __launch_bounds__(SCAN_BLK) scan_final() {
    __shared__ int buf[2][SCAN_BLK];
    int i = blockIdx.x * SCAN_BLK + threadIdx.x;
    int t = threadIdx.x;
    buf[0][t] = (i < N_NODES) ? g_deg[i] : 0;
    __syncthreads();
    int pin = 0;
    #pragma unroll
    for (int st = 1; st < SCAN_BLK; st <<= 1) {
        int v = buf[pin][t];
        if (t >= st) v += buf[pin][t - st];
        buf[pin ^ 1][t] = v;
        pin ^= 1;
        __syncthreads();
    }
    // inclusive -> exclusive
    if (i < N_NODES) {
        int excl = (t == 0) ? 0 : buf[pin][t - 1];
        g_off[i] = g_part[blockIdx.x] + excl;
    }
}

__global__ void __launch_bounds__(256) csr_fill(
    const int* __restrict__ src, const int* __restrict__ dst) {
    int e = blockIdx.x * 256 + threadIdx.x;              // N_EDGES exact
    int d = dst[e];
    int slot = atomicAdd(&g_cur[d], 1);
    g_col[g_off[d] + slot] = src[e];
}

// ---------------------------------------------------------------------------
// gather: agg[n] = h[n] + sum_{s in in-nbrs(n)} h[s]   (no atomics, no copy)
// one warp per node; lane owns a 16B chunk of the 512B row.
// ---------------------------------------------------------------------------
__global__ void __launch_bounds__(256) gather_agg(const float* __restrict__ h) {
    int gw = (blockIdx.x * 256 + threadIdx.x) >> 5;      // node; 12500 blocks = 100000 warps exact
    int lane = threadIdx.x & 31;
    const float4* hv = (const float4*)h;
    float4 acc = hv[(size_t)gw * 32 + lane];             // self term
    int beg = g_off[gw];
    int end = g_off[gw + 1];
    #pragma unroll 4
    for (int j = beg; j < end; j++) {
        int s = __ldg(&g_col[j]);                        // warp-uniform broadcast
        float4 v = hv[(size_t)s * 32 + lane];
        acc.x += v.x; acc.y += v.y; acc.z += v.z; acc.w += v.w;
    }
    ((float4*)g_agg)[(size_t)gw * 32 + lane] = acc;
}

// ---------------------------------------------------------------------------
// Fused 2-layer MLP: out = relu(relu(in@W1 + b1)@W2 + b2)
// 64-row tiles, W1+W2+tile all in SMEM (192KB), 8x4 register blocking.
// ---------------------------------------------------------------------------
__global__ void __launch_bounds__(256) mlp2(
    const float* __restrict__ in,
    const float* __restrict__ W1g, const float* __restrict__ b1g,
    const float* __restrict__ W2g, const float* __restrict__ b2g,
    float* __restrict__ out, int nrows)
{
    extern __shared__ float s[];
    float* sW1  = s;                 // 16384 floats
    float* sW2  = s + 16384;         // 16384 floats
    float* sIn  = s + 32768;         // 8192  floats (64 x 128)
    float* sMid = s + 40960;         // 8192  floats

    const int tid = threadIdx.x;

    {
        const float4* W14 = (const float4*)W1g;
        const float4* W24 = (const float4*)W2g;
        float4* sW14 = (float4*)sW1;
        float4* sW24 = (float4*)sW2;
        #pragma unroll 4
        for (int i = tid; i < 4096; i += 256) { sW14[i] = W14[i]; sW24[i] = W24[i]; }
    }

    const int row0 = blockIdx.x * 64;

    {
        float4* sIn4 = (float4*)sIn;
        #pragma unroll 2
        for (int i = tid; i < 64 * 32; i += 256) {
            int r = i >> 5;
            int gr = row0 + r;
            float4 v = make_float4(0.f, 0.f, 0.f, 0.f);
            if (gr < nrows) v = ((const float4*)(in + (size_t)gr * HID))[i & 31];
            sIn4[i] = v;
        }
    }
    __syncthreads();

    const int cg = tid & 31;
    const int rg = tid >> 5;

    float acc[8][4];

    // ---- GEMM1 ----
    {
        float4 bv = ((const float4*)b1g)[cg];
        #pragma unroll
        for (int j = 0; j < 8; j++) { acc[j][0]=bv.x; acc[j][1]=bv.y; acc[j][2]=bv.z; acc[j][3]=bv.w; }

        const float4* sW14 = (const float4*)sW1;
        #pragma unroll 4
        for (int k = 0; k < HID; k++) {
            float4 w = sW14[k * 32 + cg];
            #pragma unroll
            for (int j = 0; j < 8; j++) {
                float a = sIn[(rg * 8 + j) * HID + k];
                acc[j][0] += a * w.x; acc[j][1] += a * w.y;
                acc[j][2] += a * w.z; acc[j][3] += a * w.w;
            }
        }
        #pragma unroll
        for (int j = 0; j < 8; j++) {
            float4 v;
            v.x = fmaxf(acc[j][0], 0.f); v.y = fmaxf(acc[j][1], 0.f);
            v.z = fmaxf(acc[j][2], 0.f); v.w = fmaxf(acc[j][3], 0.f);
            ((float4*)(sMid + (rg * 8 + j) * HID))[cg] = v;
        }
    }
    __syncthreads();

    // ---- GEMM2 ----
    {
        float4 bv = ((const float4*)b2g)[cg];
        #pragma unroll
        for (int j = 0; j < 8; j++) { acc[j][0]=bv.x; acc[j][1]=bv.y; acc[j][2]=bv.z; acc[j][3]=bv.w; }

        const float4* sW24 = (const float4*)sW2;
        #pragma unroll 4
        for (int k = 0; k < HID; k++) {
            float4 w = sW24[k * 32 + cg];
            #pragma unroll
            for (int j = 0; j < 8; j++) {
                float a = sMid[(rg * 8 + j) * HID + k];
                acc[j][0] += a * w.x; acc[j][1] += a * w.y;
                acc[j][2] += a * w.z; acc[j][3] += a * w.w;
            }
        }
        #pragma unroll
        for (int j = 0; j < 8; j++) {
            int gr = row0 + rg * 8 + j;
            if (gr < nrows) {
                float4 v;
                v.x = fmaxf(acc[j][0], 0.f); v.y = fmaxf(acc[j][1], 0.f);
                v.z = fmaxf(acc[j][2], 0.f); v.w = fmaxf(acc[j][3], 0.f);
                ((float4*)(out + (size_t)gr * HID))[cg] = v;
            }
        }
    }
}

// ---------------------------------------------------------------------------
__global__ void __launch_bounds__(256) zero_pool() {
    int i = blockIdx.x * 256 + threadIdx.x;
    g_pool[i] = 0.f;
}

__global__ void __launch_bounds__(128) pool_sum(
    const float* __restrict__ h, const int* __restrict__ batch)
{
    const int CHUNK = 256;
    int col = threadIdx.x;
    int n0 = blockIdx.x * CHUNK;
    int n1 = n0 + CHUNK; if (n1 > N_NODES) n1 = N_NODES;
    if (n0 >= N_NODES) return;

    int cur = batch[n0];
    float acc = 0.f;
    for (int n = n0; n < n1; n++) {
        int b = batch[n];
        if (b != cur) {
            atomicAdd(&g_pool[(size_t)cur * HID + col], acc);
            acc = 0.f;
            cur = b;
        }
        acc += h[(size_t)n * HID + col];
    }
    atomicAdd(&g_pool[(size_t)cur * HID + col], acc);
}

__global__ void __launch_bounds__(128) heads(
    const float* __restrict__ Wmu, const float* __restrict__ bmu,
    const float* __restrict__ Wlv, const float* __restrict__ blv,
    float* __restrict__ out)
{
    __shared__ float sg[HID];
    int gi = blockIdx.x;
    sg[threadIdx.x] = g_pool[(size_t)gi * HID + threadIdx.x];
    __syncthreads();

    int t = threadIdx.x;
    const float* W = (t < LAT) ? Wmu : Wlv;
    const float* b = (t < LAT) ? bmu : blv;
    int c = t & (LAT - 1);
    float acc = b[c];
    #pragma unroll 8
    for (int k = 0; k < HID; k++) acc += sg[k] * W[k * LAT + c];

    float* o = (t < LAT) ? out : (out + (size_t)N_GRAPHS * LAT);
    o[(size_t)gi * LAT + c] = acc;
}

// ---------------------------------------------------------------------------

extern "C" void kernel_launch(void* const* d_in, const int* in_sizes, int n_in,
                              void* d_out, int out_size) {
    const float* x     = (const float*)d_in[0];
    const int*   ei    = (const int*)d_in[1];   // [2, N_EDGES] int32
    const int*   batch = (const int*)d_in[2];   // [N_NODES] int32, sorted
    const float* W1    = (const float*)d_in[3];
    const float* b1    = (const float*)d_in[4];
    const float* W2    = (const float*)d_in[5];
    const float* b2    = (const float*)d_in[6];
    const float* Wmu   = (const float*)d_in[7];
    const float* bmu   = (const float*)d_in[8];
    const float* Wlv   = (const float*)d_in[9];
    const float* blv   = (const float*)d_in[10];
    float*       out   = (float*)d_out;

    cudaFuncSetAttribute(mlp2, cudaFuncAttributeMaxDynamicSharedMemorySize, 196608);

    const int* src = ei;
    const int* dst = ei + N_EDGES;

    float* h_ptr;   cudaGetSymbolAddress((void**)&h_ptr, g_h);
    float* agg_ptr; cudaGetSymbolAddress((void**)&agg_ptr, g_agg);

    // ---- CSR build (once per launch; edge list constant) ----
    csr_zero<<<(N_NODES + 255) / 256, 256>>>();
    csr_hist<<<N_EDGES / 256, 256>>>(dst);
    scan_partial<<<SCAN_NB, SCAN_BLK>>>();
    scan_single<<<1, 32>>>();
    scan_final<<<SCAN_NB, SCAN_BLK>>>();
    csr_fill<<<N_EDGES / 256, 256>>>(src, dst);

    const int MLP_BLOCKS = (N_NODES + 63) / 64;          // 1563

    const float* cur = x;
    for (int l = 0; l < N_LAYERS; l++) {
        gather_agg<<<(N_NODES * 32) / 256, 256>>>(cur);  // agg = cur + scatter (no atomics)
        mlp2<<<MLP_BLOCKS, 256, 196608>>>(agg_ptr,
                                          W1 + (size_t)l * HID * HID, b1 + (size_t)l * HID,
                                          W2 + (size_t)l * HID * HID, b2 + (size_t)l * HID,
                                          h_ptr, N_NODES);
        cur = h_ptr;
    }

    zero_pool<<<(N_GRAPHS * HID) / 256, 256>>>();
    pool_sum<<<(N_NODES + 255) / 256, 128>>>(cur, batch);
    heads<<<N_GRAPHS, 128>>>(Wmu, bmu, Wlv, blv, out);
}

// round 8
// speedup vs baseline: 2.4406x; 1.0444x over previous
#include <cuda_runtime.h>
#include <cuda_bf16.h>

#define N_NODES  100000
#define N_EDGES  1600000
#define HID      128
#define LAT      64
#define N_LAYERS 3
#define N_GRAPHS 1000

#define SCAN_BLK 512
#define SCAN_NB  ((N_NODES + SCAN_BLK - 1) / SCAN_BLK)   // 196

// Scratch (allocation-free rule: __device__ globals)
__device__ __align__(128) float g_agg[(size_t)N_NODES * HID];
__device__ __align__(128) float g_h[(size_t)N_NODES * HID];
__device__ __align__(128) float g_pool[(size_t)N_GRAPHS * HID];
// CSR build scratch
__device__ int g_deg[N_NODES];
__device__ int g_cur[N_NODES];
__device__ int g_off[N_NODES + 1];
__device__ int g_col[N_EDGES];
__device__ int g_part[SCAN_NB];

// packed-fp32 helpers (sm_103a fma.rn.f32x2 — ptxas never emits this from C++)
#define PACK2(d, lo, hi) asm("mov.b64 %0, {%1, %2};" : "=l"(d) : "f"(lo), "f"(hi))
#define UNPACK2(lo, hi, s) asm("mov.b64 {%0, %1}, %2;" : "=f"(lo), "=f"(hi) : "l"(s))
#define FMA2(d, a, b, c) asm("fma.rn.f32x2 %0, %1, %2, %3;" : "=l"(d) : "l"(a), "l"(b), "l"(c))

// ---------------------------------------------------------------------------
// CSR build: histogram -> 2-level exclusive scan -> placement
// ---------------------------------------------------------------------------
__global__ void __launch_bounds__(256) csr_zero() {
    int i = blockIdx.x * 256 + threadIdx.x;
    if (i < N_NODES) { g_deg[i] = 0; g_cur[i] = 0; }
}

__global__ void __launch_bounds__(256) csr_hist(const int* __restrict__ dst) {
    int e = blockIdx.x * 256 + threadIdx.x;              // N_EDGES exact (6250 blocks)
    atomicAdd(&g_deg[dst[e]], 1);
}

__global__ void __launch_bounds__(SCAN_BLK) scan_partial() {
    __shared__ int sm[SCAN_BLK];
    int i = blockIdx.x * SCAN_BLK + threadIdx.x;
    sm[threadIdx.x] = (i < N_NODES) ? g_deg[i] : 0;
    __syncthreads();
    for (int st = SCAN_BLK / 2; st > 0; st >>= 1) {
        if (threadIdx.x < st) sm[threadIdx.x] += sm[threadIdx.x + st];
        __syncthreads();
    }
    if (threadIdx.x == 0) g_part[blockIdx.x] = sm[0];
}

__global__ void __launch_bounds__(32) scan_single() {
    if (threadIdx.x == 0) {
        int acc = 0;
        for (int b = 0; b < SCAN_NB; b++) { int v = g_part[b]; g_part[b] = acc; acc += v; }
        g_off[N_NODES] = N_EDGES;
    }
}

__global__ void __launch_bounds__(SCAN_BLK) scan_final() {
    __shared__ int buf[2][SCAN_BLK];
    int i = blockIdx.x * SCAN_BLK + threadIdx.x;
    int t = threadIdx.x;
    buf[0][t] = (i < N_NODES) ? g_deg[i] : 0;
    __syncthreads();
    int pin = 0;
    #pragma unroll
    for (int st = 1; st < SCAN_BLK; st <<= 1) {
        int v = buf[pin][t];
        if (t >= st) v += buf[pin][t - st];
        buf[pin ^ 1][t] = v;
        pin ^= 1;
        __syncthreads();
    }
    if (i < N_NODES) {
        int excl = (t == 0) ? 0 : buf[pin][t - 1];
        g_off[i] = g_part[blockIdx.x] + excl;
    }
}

__global__ void __launch_bounds__(256) csr_fill(
    const int* __restrict__ src, const int* __restrict__ dst) {
    int e = blockIdx.x * 256 + threadIdx.x;              // N_EDGES exact
    int d = dst[e];
    int slot = atomicAdd(&g_cur[d], 1);
    g_col[g_off[d] + slot] = src[e];
}

// ---------------------------------------------------------------------------
// gather: agg[n] = h[n] + sum_{s in in-nbrs(n)} h[s]   (no atomics, no copy)
// ---------------------------------------------------------------------------
__global__ void __launch_bounds__(256) gather_agg(const float* __restrict__ h) {
    int gw = (blockIdx.x * 256 + threadIdx.x) >> 5;      // node; 100000 warps exact
    int lane = threadIdx.x & 31;
    const float4* hv = (const float4*)h;
    float4 acc = hv[(size_t)gw * 32 + lane];             // self term
    int beg = g_off[gw];
    int end = g_off[gw + 1];
    #pragma unroll 4
    for (int j = beg; j < end; j++) {
        int s = __ldg(&g_col[j]);
        float4 v = hv[(size_t)s * 32 + lane];
        acc.x += v.x; acc.y += v.y; acc.z += v.z; acc.w += v.w;
    }
    ((float4*)g_agg)[(size_t)gw * 32 + lane] = acc;
}

// ---------------------------------------------------------------------------
// Fused 2-layer MLP with packed fma.rn.f32x2 (exact fp32, 2 FMAs/issue).
// 64-row tiles; W1+W2+tiles in 192KB SMEM; per thread 8 rows x 4 cols.
// W read as ulonglong2 -> packed pairs come free from the 128-bit load.
// ---------------------------------------------------------------------------
__global__ void __launch_bounds__(256) mlp2(
    const float* __restrict__ in,
    const float* __restrict__ W1g, const float* __restrict__ b1g,
    const float* __restrict__ W2g, const float* __restrict__ b2g,
    float* __restrict__ out, int nrows)
{
    extern __shared__ float s[];
    float* sW1  = s;                 // 16384 floats
    float* sW2  = s + 16384;
    float* sIn  = s + 32768;         // 8192 floats (64 x 128)
    float* sMid = s + 40960;

    const int tid = threadIdx.x;

    {
        const float4* W14 = (const float4*)W1g;
        const float4* W24 = (const float4*)W2g;
        float4* sW14 = (float4*)sW1;
        float4* sW24 = (float4*)sW2;
        #pragma unroll 4
        for (int i = tid; i < 4096; i += 256) { sW14[i] = W14[i]; sW24[i] = W24[i]; }
    }

    const int row0 = blockIdx.x * 64;

    {
        float4* sIn4 = (float4*)sIn;
        #pragma unroll 2
        for (int i = tid; i < 64 * 32; i += 256) {
            int r = i >> 5;
            int gr = row0 + r;
            float4 v = make_float4(0.f, 0.f, 0.f, 0.f);
            if (gr < nrows) v = ((const float4*)(in + (size_t)gr * HID))[i & 31];
            sIn4[i] = v;
        }
    }
    __syncthreads();

    const int cg = tid & 31;   // 4 output cols: 4*cg..4*cg+3
    const int rg = tid >> 5;   // 8 rows: rg*8..rg*8+7

    unsigned long long acc[8][2];

    // ---- GEMM1: mid = relu(in @ W1 + b1) ----
    {
        float4 bv = ((const float4*)b1g)[cg];
        unsigned long long b01, b23;
        PACK2(b01, bv.x, bv.y); PACK2(b23, bv.z, bv.w);
        #pragma unroll
        for (int j = 0; j < 8; j++) { acc[j][0] = b01; acc[j][1] = b23; }

        const ulonglong2* sW = (const ulonglong2*)sW1;
        const float4* sA = (const float4*)sIn;
        #pragma unroll 2
        for (int kg = 0; kg < 32; kg++) {
            ulonglong2 w0 = sW[(4*kg+0)*32 + cg];
            ulonglong2 w1 = sW[(4*kg+1)*32 + cg];
            ulonglong2 w2 = sW[(4*kg+2)*32 + cg];
            ulonglong2 w3 = sW[(4*kg+3)*32 + cg];
            #pragma unroll
            for (int j = 0; j < 8; j++) {
                float4 av = sA[(rg*8+j)*32 + kg];
                unsigned long long p;
                PACK2(p, av.x, av.x);
                FMA2(acc[j][0], p, w0.x, acc[j][0]); FMA2(acc[j][1], p, w0.y, acc[j][1]);
                PACK2(p, av.y, av.y);
                FMA2(acc[j][0], p, w1.x, acc[j][0]); FMA2(acc[j][1], p, w1.y, acc[j][1]);
                PACK2(p, av.z, av.z);
                FMA2(acc[j][0], p, w2.x, acc[j][0]); FMA2(acc[j][1], p, w2.y, acc[j][1]);
                PACK2(p, av.w, av.w);
                FMA2(acc[j][0], p, w3.x, acc[j][0]); FMA2(acc[j][1], p, w3.y, acc[j][1]);
            }
        }
        #pragma unroll
        for (int j = 0; j < 8; j++) {
            float4 v;
            UNPACK2(v.x, v.y, acc[j][0]);
            UNPACK2(v.z, v.w, acc[j][1]);
            v.x = fmaxf(v.x, 0.f); v.y = fmaxf(v.y, 0.f);
            v.z = fmaxf(v.z, 0.f); v.w = fmaxf(v.w, 0.f);
            ((float4*)(sMid + (rg*8+j) * HID))[cg] = v;
        }
    }
    __syncthreads();

    // ---- GEMM2: out = relu(mid @ W2 + b2) ----
    {
        float4 bv = ((const float4*)b2g)[cg];
        unsigned long long b01, b23;
        PACK2(b01, bv.x, bv.y); PACK2(b23, bv.z, bv.w);
        #pragma unroll
        for (int j = 0; j < 8; j++) { acc[j][0] = b01; acc[j][1] = b23; }

        const ulonglong2* sW = (const ulonglong2*)sW2;
        const float4* sA = (const float4*)sMid;
        #pragma unroll 2
        for (int kg = 0; kg < 32; kg++) {
            ulonglong2 w0 = sW[(4*kg+0)*32 + cg];
            ulonglong2 w1 = sW[(4*kg+1)*32 + cg];
            ulonglong2 w2 = sW[(4*kg+2)*32 + cg];
            ulonglong2 w3 = sW[(4*kg+3)*32 + cg];
            #pragma unroll
            for (int j = 0; j < 8; j++) {
                float4 av = sA[(rg*8+j)*32 + kg];
                unsigned long long p;
                PACK2(p, av.x, av.x);
                FMA2(acc[j][0], p, w0.x, acc[j][0]); FMA2(acc[j][1], p, w0.y, acc[j][1]);
                PACK2(p, av.y, av.y);
                FMA2(acc[j][0], p, w1.x, acc[j][0]); FMA2(acc[j][1], p, w1.y, acc[j][1]);
                PACK2(p, av.z, av.z);
                FMA2(acc[j][0], p, w2.x, acc[j][0]); FMA2(acc[j][1], p, w2.y, acc[j][1]);
                PACK2(p, av.w, av.w);
                FMA2(acc[j][0], p, w3.x, acc[j][0]); FMA2(acc[j][1], p, w3.y, acc[j][1]);
            }
        }
        #pragma unroll
        for (int j = 0; j < 8; j++) {
            int gr = row0 + rg*8 + j;
            if (gr < nrows) {
                float4 v;
                UNPACK2(v.x, v.y, acc[j][0]);
                UNPACK2(v.z, v.w, acc[j][1]);
                v.x = fmaxf(v.x, 0.f); v.y = fmaxf(v.y, 0.f);
                v.z = fmaxf(v.z, 0.f); v.w = fmaxf(v.w, 0.f);
                ((float4*)(out + (size_t)gr * HID))[cg] = v;
            }
        }
    }
}

// ---------------------------------------------------------------------------
__global__ void __launch_bounds__(256) zero_pool() {
    int i = blockIdx.x * 256 + threadIdx.x;
    g_pool[i] = 0.f;
}

__global__ void __launch_bounds__(128) pool_sum(
    const float* __restrict__ h, const int* __restrict__ batch)
{
    const int CHUNK = 256;
    int col = threadIdx.x;
    int n0 = blockIdx.x * CHUNK;
    int n1 = n0 + CHUNK; if (n1 > N_NODES) n1 = N_NODES;
    if (n0 >= N_NODES) return;

    int cur = batch[n0];
    float acc = 0.f;
    for (int n = n0; n < n1; n++) {
        int b = batch[n];
        if (b != cur) {
            atomicAdd(&g_pool[(size_t)cur * HID + col], acc);
            acc = 0.f;
            cur = b;
        }
        acc += h[(size_t)n * HID + col];
    }
    atomicAdd(&g_pool[(size_t)cur * HID + col], acc);
}

__global__ void __launch_bounds__(128) heads(
    const float* __restrict__ Wmu, const float* __restrict__ bmu,
    const float* __restrict__ Wlv, const float* __restrict__ blv,
    float* __restrict__ out)
{
    __shared__ float sg[HID];
    int gi = blockIdx.x;
    sg[threadIdx.x] = g_pool[(size_t)gi * HID + threadIdx.x];
    __syncthreads();

    int t = threadIdx.x;
    const float* W = (t < LAT) ? Wmu : Wlv;
    const float* b = (t < LAT) ? bmu : blv;
    int c = t & (LAT - 1);
    float acc = b[c];
    #pragma unroll 8
    for (int k = 0; k < HID; k++) acc += sg[k] * W[k * LAT + c];

    float* o = (t < LAT) ? out : (out + (size_t)N_GRAPHS * LAT);
    o[(size_t)gi * LAT + c] = acc;
}

// ---------------------------------------------------------------------------

extern "C" void kernel_launch(void* const* d_in, const int* in_sizes, int n_in,
                              void* d_out, int out_size) {
    const float* x     = (const float*)d_in[0];
    const int*   ei    = (const int*)d_in[1];
    const int*   batch = (const int*)d_in[2];
    const float* W1    = (const float*)d_in[3];
    const float* b1    = (const float*)d_in[4];
    const float* W2    = (const float*)d_in[5];
    const float* b2    = (const float*)d_in[6];
    const float* Wmu   = (const float*)d_in[7];
    const float* bmu   = (const float*)d_in[8];
    const float* Wlv   = (const float*)d_in[9];
    const float* blv   = (const float*)d_in[10];
    float*       out   = (float*)d_out;

    cudaFuncSetAttribute(mlp2, cudaFuncAttributeMaxDynamicSharedMemorySize, 196608);

    const int* src = ei;
    const int* dst = ei + N_EDGES;

    float* h_ptr;   cudaGetSymbolAddress((void**)&h_ptr, g_h);
    float* agg_ptr; cudaGetSymbolAddress((void**)&agg_ptr, g_agg);

    // ---- CSR build (once per launch; edge list constant) ----
    csr_zero<<<(N_NODES + 255) / 256, 256>>>();
    csr_hist<<<N_EDGES / 256, 256>>>(dst);
    scan_partial<<<SCAN_NB, SCAN_BLK>>>();
    scan_single<<<1, 32>>>();
    scan_final<<<SCAN_NB, SCAN_BLK>>>();
    csr_fill<<<N_EDGES / 256, 256>>>(src, dst);

    const int MLP_BLOCKS = (N_NODES + 63) / 64;          // 1563

    const float* cur = x;
    for (int l = 0; l < N_LAYERS; l++) {
        gather_agg<<<(N_NODES * 32) / 256, 256>>>(cur);
        mlp2<<<MLP_BLOCKS, 256, 196608>>>(agg_ptr,
                                          W1 + (size_t)l * HID * HID, b1 + (size_t)l * HID,
                                          W2 + (size_t)l * HID * HID, b2 + (size_t)l * HID,
                                          h_ptr, N_NODES);
        cur = h_ptr;
    }

    zero_pool<<<(N_GRAPHS * HID) / 256, 256>>>();
    pool_sum<<<(N_NODES + 255) / 256, 128>>>(cur, batch);
    heads<<<N_GRAPHS, 128>>>(Wmu, bmu, Wlv, blv, out);
}

// round 9
// speedup vs baseline: 2.4424x; 1.0008x over previous
#include <cuda_runtime.h>
#include <cuda_bf16.h>

#define N_NODES  100000
#define N_EDGES  1600000
#define HID      128
#define LAT      64
#define N_LAYERS 3
#define N_GRAPHS 1000

#define SCAN_BLK 512
#define SCAN_NB  ((N_NODES + SCAN_BLK - 1) / SCAN_BLK)   // 196

// Scratch (allocation-free rule: __device__ globals)
__device__ __align__(128) float g_agg[(size_t)N_NODES * HID];
__device__ __align__(128) float g_h[(size_t)N_NODES * HID];
__device__ __align__(128) float g_pool[(size_t)N_GRAPHS * HID];
// CSR build scratch
__device__ int g_deg[N_NODES];
__device__ int g_cur[N_NODES];
__device__ int g_off[N_NODES + 1];
__device__ int g_col[N_EDGES];
__device__ int g_part[SCAN_NB];

// packed-fp32 helpers (sm_103a fma.rn.f32x2 — ptxas never emits this from C++)
#define PACK2(d, lo, hi) asm("mov.b64 %0, {%1, %2};" : "=l"(d) : "f"(lo), "f"(hi))
#define UNPACK2(lo, hi, s) asm("mov.b64 {%0, %1}, %2;" : "=f"(lo), "=f"(hi) : "l"(s))
#define FMA2(d, a, b, c) asm("fma.rn.f32x2 %0, %1, %2, %3;" : "=l"(d) : "l"(a), "l"(b), "l"(c))

// ---------------------------------------------------------------------------
// CSR build: histogram -> 2-level exclusive scan -> placement
// ---------------------------------------------------------------------------
__global__ void __launch_bounds__(256) csr_zero() {
    int i = blockIdx.x * 256 + threadIdx.x;
    if (i < N_NODES) { g_deg[i] = 0; g_cur[i] = 0; }
}

__global__ void __launch_bounds__(256) csr_hist(const int* __restrict__ dst) {
    int e = blockIdx.x * 256 + threadIdx.x;              // N_EDGES exact (6250 blocks)
    atomicAdd(&g_deg[dst[e]], 1);
}

__global__ void __launch_bounds__(SCAN_BLK) scan_partial() {
    __shared__ int sm[SCAN_BLK];
    int i = blockIdx.x * SCAN_BLK + threadIdx.x;
    sm[threadIdx.x] = (i < N_NODES) ? g_deg[i] : 0;
    __syncthreads();
    for (int st = SCAN_BLK / 2; st > 0; st >>= 1) {
        if (threadIdx.x < st) sm[threadIdx.x] += sm[threadIdx.x + st];
        __syncthreads();
    }
    if (threadIdx.x == 0) g_part[blockIdx.x] = sm[0];
}

__global__ void __launch_bounds__(32) scan_single() {
    if (threadIdx.x == 0) {
        int acc = 0;
        for (int b = 0; b < SCAN_NB; b++) { int v = g_part[b]; g_part[b] = acc; acc += v; }
        g_off[N_NODES] = N_EDGES;
    }
}

__global__ void __launch_bounds__(SCAN_BLK) scan_final() {
    __shared__ int buf[2][SCAN_BLK];
    int i = blockIdx.x * SCAN_BLK + threadIdx.x;
    int t = threadIdx.x;
    buf[0][t] = (i < N_NODES) ? g_deg[i] : 0;
    __syncthreads();
    int pin = 0;
    #pragma unroll
    for (int st = 1; st < SCAN_BLK; st <<= 1) {
        int v = buf[pin][t];
        if (t >= st) v += buf[pin][t - st];
        buf[pin ^ 1][t] = v;
        pin ^= 1;
        __syncthreads();
    }
    if (i < N_NODES) {
        int excl = (t == 0) ? 0 : buf[pin][t - 1];
        g_off[i] = g_part[blockIdx.x] + excl;
    }
}

__global__ void __launch_bounds__(256) csr_fill(
    const int* __restrict__ src, const int* __restrict__ dst) {
    int e = blockIdx.x * 256 + threadIdx.x;              // N_EDGES exact
    int d = dst[e];
    int slot = atomicAdd(&g_cur[d], 1);
    g_col[g_off[d] + slot] = src[e];
}

// ---------------------------------------------------------------------------
// gather: agg[n] = h[n] + sum_{s in in-nbrs(n)} h[s]   (no atomics, no copy)
// ---------------------------------------------------------------------------
__global__ void __launch_bounds__(256) gather_agg(const float* __restrict__ h) {
    int gw = (blockIdx.x * 256 + threadIdx.x) >> 5;      // node; 100000 warps exact
    int lane = threadIdx.x & 31;
    const float4* hv = (const float4*)h;
    float4 acc = hv[(size_t)gw * 32 + lane];             // self term
    int beg = g_off[gw];
    int end = g_off[gw + 1];
    #pragma unroll 4
    for (int j = beg; j < end; j++) {
        int s = __ldg(&g_col[j]);
        float4 v = hv[(size_t)s * 32 + lane];
        acc.x += v.x; acc.y += v.y; acc.z += v.z; acc.w += v.w;
    }
    ((float4*)g_agg)[(size_t)gw * 32 + lane] = acc;
}

// ---------------------------------------------------------------------------
// Fused 2-layer MLP with packed fma.rn.f32x2 (exact fp32, 2 FMAs/issue).
// 64-row tiles; W1+W2+tiles in 192KB SMEM; per thread 8 rows x 4 cols.
// W read as ulonglong2 -> packed pairs come free from the 128-bit load.
// ---------------------------------------------------------------------------
__global__ void __launch_bounds__(256) mlp2(
    const float* __restrict__ in,
    const float* __restrict__ W1g, const float* __restrict__ b1g,
    const float* __restrict__ W2g, const float* __restrict__ b2g,
    float* __restrict__ out, int nrows)
{
    extern __shared__ float s[];
    float* sW1  = s;                 // 16384 floats
    float* sW2  = s + 16384;
    float* sIn  = s + 32768;         // 8192 floats (64 x 128)
    float* sMid = s + 40960;

    const int tid = threadIdx.x;

    {
        const float4* W14 = (const float4*)W1g;
        const float4* W24 = (const float4*)W2g;
        float4* sW14 = (float4*)sW1;
        float4* sW24 = (float4*)sW2;
        #pragma unroll 4
        for (int i = tid; i < 4096; i += 256) { sW14[i] = W14[i]; sW24[i] = W24[i]; }
    }

    const int row0 = blockIdx.x * 64;

    {
        float4* sIn4 = (float4*)sIn;
        #pragma unroll 2
        for (int i = tid; i < 64 * 32; i += 256) {
            int r = i >> 5;
            int gr = row0 + r;
            float4 v = make_float4(0.f, 0.f, 0.f, 0.f);
            if (gr < nrows) v = ((const float4*)(in + (size_t)gr * HID))[i & 31];
            sIn4[i] = v;
        }
    }
    __syncthreads();

    const int cg = tid & 31;   // 4 output cols: 4*cg..4*cg+3
    const int rg = tid >> 5;   // 8 rows: rg*8..rg*8+7

    unsigned long long acc[8][2];

    // ---- GEMM1: mid = relu(in @ W1 + b1) ----
    {
        float4 bv = ((const float4*)b1g)[cg];
        unsigned long long b01, b23;
        PACK2(b01, bv.x, bv.y); PACK2(b23, bv.z, bv.w);
        #pragma unroll
        for (int j = 0; j < 8; j++) { acc[j][0] = b01; acc[j][1] = b23; }

        const ulonglong2* sW = (const ulonglong2*)sW1;
        const float4* sA = (const float4*)sIn;
        #pragma unroll 2
        for (int kg = 0; kg < 32; kg++) {
            ulonglong2 w0 = sW[(4*kg+0)*32 + cg];
            ulonglong2 w1 = sW[(4*kg+1)*32 + cg];
            ulonglong2 w2 = sW[(4*kg+2)*32 + cg];
            ulonglong2 w3 = sW[(4*kg+3)*32 + cg];
            #pragma unroll
            for (int j = 0; j < 8; j++) {
                float4 av = sA[(rg*8+j)*32 + kg];
                unsigned long long p;
                PACK2(p, av.x, av.x);
                FMA2(acc[j][0], p, w0.x, acc[j][0]); FMA2(acc[j][1], p, w0.y, acc[j][1]);
                PACK2(p, av.y, av.y);
                FMA2(acc[j][0], p, w1.x, acc[j][0]); FMA2(acc[j][1], p, w1.y, acc[j][1]);
                PACK2(p, av.z, av.z);
                FMA2(acc[j][0], p, w2.x, acc[j][0]); FMA2(acc[j][1], p, w2.y, acc[j][1]);
                PACK2(p, av.w, av.w);
                FMA2(acc[j][0], p, w3.x, acc[j][0]); FMA2(acc[j][1], p, w3.y, acc[j][1]);
            }
        }
        #pragma unroll
        for (int j = 0; j < 8; j++) {
            float4 v;
            UNPACK2(v.x, v.y, acc[j][0]);
            UNPACK2(v.z, v.w, acc[j][1]);
            v.x = fmaxf(v.x, 0.f); v.y = fmaxf(v.y, 0.f);
            v.z = fmaxf(v.z, 0.f); v.w = fmaxf(v.w, 0.f);
            ((float4*)(sMid + (rg*8+j) * HID))[cg] = v;
        }
    }
    __syncthreads();

    // ---- GEMM2: out = relu(mid @ W2 + b2) ----
    {
        float4 bv = ((const float4*)b2g)[cg];
        unsigned long long b01, b23;
        PACK2(b01, bv.x, bv.y); PACK2(b23, bv.z, bv.w);
        #pragma unroll
        for (int j = 0; j < 8; j++) { acc[j][0] = b01; acc[j][1] = b23; }

        const ulonglong2* sW = (const ulonglong2*)sW2;
        const float4* sA = (const float4*)sMid;
        #pragma unroll 2
        for (int kg = 0; kg < 32; kg++) {
            ulonglong2 w0 = sW[(4*kg+0)*32 + cg];
            ulonglong2 w1 = sW[(4*kg+1)*32 + cg];
            ulonglong2 w2 = sW[(4*kg+2)*32 + cg];
            ulonglong2 w3 = sW[(4*kg+3)*32 + cg];
            #pragma unroll
            for (int j = 0; j < 8; j++) {
                float4 av = sA[(rg*8+j)*32 + kg];
                unsigned long long p;
                PACK2(p, av.x, av.x);
                FMA2(acc[j][0], p, w0.x, acc[j][0]); FMA2(acc[j][1], p, w0.y, acc[j][1]);
                PACK2(p, av.y, av.y);
                FMA2(acc[j][0], p, w1.x, acc[j][0]); FMA2(acc[j][1], p, w1.y, acc[j][1]);
                PACK2(p, av.z, av.z);
                FMA2(acc[j][0], p, w2.x, acc[j][0]); FMA2(acc[j][1], p, w2.y, acc[j][1]);
                PACK2(p, av.w, av.w);
                FMA2(acc[j][0], p, w3.x, acc[j][0]); FMA2(acc[j][1], p, w3.y, acc[j][1]);
            }
        }
        #pragma unroll
        for (int j = 0; j < 8; j++) {
            int gr = row0 + rg*8 + j;
            if (gr < nrows) {
                float4 v;
                UNPACK2(v.x, v.y, acc[j][0]);
                UNPACK2(v.z, v.w, acc[j][1]);
                v.x = fmaxf(v.x, 0.f); v.y = fmaxf(v.y, 0.f);
                v.z = fmaxf(v.z, 0.f); v.w = fmaxf(v.w, 0.f);
                ((float4*)(out + (size_t)gr * HID))[cg] = v;
            }
        }
    }
}

// ---------------------------------------------------------------------------
__global__ void __launch_bounds__(256) zero_pool() {
    int i = blockIdx.x * 256 + threadIdx.x;
    g_pool[i] = 0.f;
}

__global__ void __launch_bounds__(128) pool_sum(
    const float* __restrict__ h, const int* __restrict__ batch)
{
    const int CHUNK = 256;
    int col = threadIdx.x;
    int n0 = blockIdx.x * CHUNK;
    int n1 = n0 + CHUNK; if (n1 > N_NODES) n1 = N_NODES;
    if (n0 >= N_NODES) return;

    int cur = batch[n0];
    float acc = 0.f;
    for (int n = n0; n < n1; n++) {
        int b = batch[n];
        if (b != cur) {
            atomicAdd(&g_pool[(size_t)cur * HID + col], acc);
            acc = 0.f;
            cur = b;
        }
        acc += h[(size_t)n * HID + col];
    }
    atomicAdd(&g_pool[(size_t)cur * HID + col], acc);
}

__global__ void __launch_bounds__(128) heads(
    const float* __restrict__ Wmu, const float* __restrict__ bmu,
    const float* __restrict__ Wlv, const float* __restrict__ blv,
    float* __restrict__ out)
{
    __shared__ float sg[HID];
    int gi = blockIdx.x;
    sg[threadIdx.x] = g_pool[(size_t)gi * HID + threadIdx.x];
    __syncthreads();

    int t = threadIdx.x;
    const float* W = (t < LAT) ? Wmu : Wlv;
    const float* b = (t < LAT) ? bmu : blv;
    int c = t & (LAT - 1);
    float acc = b[c];
    #pragma unroll 8
    for (int k = 0; k < HID; k++) acc += sg[k] * W[k * LAT + c];

    float* o = (t < LAT) ? out : (out + (size_t)N_GRAPHS * LAT);
    o[(size_t)gi * LAT + c] = acc;
}

// ---------------------------------------------------------------------------

extern "C" void kernel_launch(void* const* d_in, const int* in_sizes, int n_in,
                              void* d_out, int out_size) {
    const float* x     = (const float*)d_in[0];
    const int*   ei    = (const int*)d_in[1];
    const int*   batch = (const int*)d_in[2];
    const float* W1    = (const float*)d_in[3];
    const float* b1    = (const float*)d_in[4];
    const float* W2    = (const float*)d_in[5];
    const float* b2    = (const float*)d_in[6];
    const float* Wmu   = (const float*)d_in[7];
    const float* bmu   = (const float*)d_in[8];
    const float* Wlv   = (const float*)d_in[9];
    const float* blv   = (const float*)d_in[10];
    float*       out   = (float*)d_out;

    cudaFuncSetAttribute(mlp2, cudaFuncAttributeMaxDynamicSharedMemorySize, 196608);

    const int* src = ei;
    const int* dst = ei + N_EDGES;

    float* h_ptr;   cudaGetSymbolAddress((void**)&h_ptr, g_h);
    float* agg_ptr; cudaGetSymbolAddress((void**)&agg_ptr, g_agg);

    // ---- CSR build (once per launch; edge list constant) ----
    csr_zero<<<(N_NODES + 255) / 256, 256>>>();
    csr_hist<<<N_EDGES / 256, 256>>>(dst);
    scan_partial<<<SCAN_NB, SCAN_BLK>>>();
    scan_single<<<1, 32>>>();
    scan_final<<<SCAN_NB, SCAN_BLK>>>();
    csr_fill<<<N_EDGES / 256, 256>>>(src, dst);

    const int MLP_BLOCKS = (N_NODES + 63) / 64;          // 1563

    const float* cur = x;
    for (int l = 0; l < N_LAYERS; l++) {
        gather_agg<<<(N_NODES * 32) / 256, 256>>>(cur);
        mlp2<<<MLP_BLOCKS, 256, 196608>>>(agg_ptr,
                                          W1 + (size_t)l * HID * HID, b1 + (size_t)l * HID,
                                          W2 + (size_t)l * HID * HID, b2 + (size_t)l * HID,
                                          h_ptr, N_NODES);
        cur = h_ptr;
    }

    zero_pool<<<(N_GRAPHS * HID) / 256, 256>>>();
    pool_sum<<<(N_NODES + 255) / 256, 128>>>(cur, batch);
    heads<<<N_GRAPHS, 128>>>(Wmu, bmu, Wlv, blv, out);
}

// round 13
// speedup vs baseline: 4.5086x; 1.8459x over previous
#include <cuda_runtime.h>
#include <cuda_bf16.h>
#include <cstdint>

#define N_NODES  100000
#define N_EDGES  1600000
#define HID      128
#define LAT      64
#define N_LAYERS 3
#define N_GRAPHS 1000

#define SCAN_BLK 512
#define SCAN_NB  ((N_NODES + SCAN_BLK - 1) / SCAN_BLK)   // 196
#define TILES    ((N_NODES + 127) / 128)                 // 782

// Scratch (allocation-free rule: __device__ globals)
__device__ __align__(128) float g_agg[(size_t)N_NODES * HID];
__device__ __align__(128) float g_h[(size_t)N_NODES * HID];
__device__ __align__(128) float g_pool[(size_t)N_GRAPHS * HID];
// CSR build scratch
__device__ int g_deg[N_NODES];
__device__ int g_cur[N_NODES];
__device__ int g_off[N_NODES + 1];
__device__ int g_col[N_EDGES];
__device__ int g_part[SCAN_NB];
// fragment-ordered weights: [layer][mat][ntile=16][kstep=8][lane=32] -> uint4{bh0,bh1,bl0,bl1}
__device__ __align__(16) uint4 g_bfrag[3 * 2 * 16 * 8 * 32];

// ---------------------------------------------------------------------------
__device__ __forceinline__ void split2(float a0, float a1, uint32_t& hi, uint32_t& lo) {
    __nv_bfloat16 h0 = __float2bfloat16(a0);
    __nv_bfloat16 h1 = __float2bfloat16(a1);
    float r0 = a0 - __bfloat162float(h0);
    float r1 = a1 - __bfloat162float(h1);
    __nv_bfloat16 l0 = __float2bfloat16(r0);
    __nv_bfloat16 l1 = __float2bfloat16(r1);
    __nv_bfloat162 H; H.x = h0; H.y = h1;
    __nv_bfloat162 L; L.x = l0; L.y = l1;
    hi = *reinterpret_cast<uint32_t*>(&H);
    lo = *reinterpret_cast<uint32_t*>(&L);
}

// m16n8k16 bf16 mma, fp32 accum (legacy tensor path; sm_80+ PTX, works on compute_103)
#define MMA_BF16(d, a, b0, b1) \
    asm volatile("mma.sync.aligned.m16n8k16.row.col.f32.bf16.bf16.f32 " \
        "{%0,%1,%2,%3}, {%4,%5,%6,%7}, {%8,%9}, {%0,%1,%2,%3};" \
        : "+f"((d)[0]), "+f"((d)[1]), "+f"((d)[2]), "+f"((d)[3]) \
        : "r"((a)[0]), "r"((a)[1]), "r"((a)[2]), "r"((a)[3]), "r"(b0), "r"(b1))

// ---------------------------------------------------------------------------
// CSR build: histogram -> 2-level exclusive scan -> placement
// ---------------------------------------------------------------------------
__global__ void __launch_bounds__(256) csr_zero() {
    int i = blockIdx.x * 256 + threadIdx.x;
    if (i < N_NODES) { g_deg[i] = 0; g_cur[i] = 0; }
}

__global__ void __launch_bounds__(256) csr_hist(const int* __restrict__ dst) {
    int e = blockIdx.x * 256 + threadIdx.x;
    atomicAdd(&g_deg[dst[e]], 1);
}

__global__ void __launch_bounds__(SCAN_BLK) scan_partial() {
    __shared__ int sm[SCAN_BLK];
    int i = blockIdx.x * SCAN_BLK + threadIdx.x;
    sm[threadIdx.x] = (i < N_NODES) ? g_deg[i] : 0;
    __syncthreads();
    for (int st = SCAN_BLK / 2; st > 0; st >>= 1) {
        if (threadIdx.x < st) sm[threadIdx.x] += sm[threadIdx.x + st];
        __syncthreads();
    }
    if (threadIdx.x == 0) g_part[blockIdx.x] = sm[0];
}

__global__ void __launch_bounds__(32) scan_single() {
    if (threadIdx.x == 0) {
        int acc = 0;
        for (int b = 0; b < SCAN_NB; b++) { int v = g_part[b]; g_part[b] = acc; acc += v; }
        g_off[N_NODES] = N_EDGES;
    }
}

__global__ void __launch_bounds__(SCAN_BLK) scan_final() {
    __shared__ int buf[2][SCAN_BLK];
    int i = blockIdx.x * SCAN_BLK + threadIdx.x;
    int t = threadIdx.x;
    buf[0][t] = (i < N_NODES) ? g_deg[i] : 0;
    __syncthreads();
    int pin = 0;
    #pragma unroll
    for (int st = 1; st < SCAN_BLK; st <<= 1) {
        int v = buf[pin][t];
        if (t >= st) v += buf[pin][t - st];
        buf[pin ^ 1][t] = v;
        pin ^= 1;
        __syncthreads();
    }
    if (i < N_NODES) {
        int excl = (t == 0) ? 0 : buf[pin][t - 1];
        g_off[i] = g_part[blockIdx.x] + excl;
    }
}

__global__ void __launch_bounds__(256) csr_fill(
    const int* __restrict__ src, const int* __restrict__ dst) {
    int e = blockIdx.x * 256 + threadIdx.x;
    int d = dst[e];
    int slot = atomicAdd(&g_cur[d], 1);
    g_col[g_off[d] + slot] = src[e];
}

// ---------------------------------------------------------------------------
// precompute B fragments (hi/lo bf16 split) in mma.sync col-major layout.
// W is [k][n] row-major; B frag for n-tile j, k-step s, lane (g=lane/4, tg=lane%4):
//   bh0 = {W[k0][n], W[k0+1][n]}, bh1 = {W[k0+8][n], W[k0+9][n]},  k0 = s*16+tg*2, n = j*8+g
// ---------------------------------------------------------------------------
__global__ void __launch_bounds__(256) split_wfrag(
    const float* __restrict__ W1, const float* __restrict__ W2) {
    int idx = blockIdx.x * 256 + threadIdx.x;            // 24576 total
    if (idx >= 3 * 2 * 16 * 8 * 32) return;
    int l    = idx >> 13;          // / 8192
    int rem  = idx & 8191;
    int mat  = rem >> 12;          // / 4096
    int rem2 = rem & 4095;
    int j    = rem2 >> 8;
    int s    = (rem2 >> 5) & 7;
    int lane = rem2 & 31;
    int g = lane >> 2, tg = lane & 3;
    int n = j * 8 + g;
    int k0 = s * 16 + tg * 2;
    const float* W = (mat ? W2 : W1) + l * 16384;
    float f00 = W[k0 * 128 + n],       f01 = W[(k0 + 1) * 128 + n];
    float f10 = W[(k0 + 8) * 128 + n], f11 = W[(k0 + 9) * 128 + n];
    uint32_t h0, l0, h1, l1;
    split2(f00, f01, h0, l0);
    split2(f10, f11, h1, l1);
    g_bfrag[idx] = make_uint4(h0, h1, l0, l1);
}

// ---------------------------------------------------------------------------
// gather: agg[n] = h[n] + sum_{s in in-nbrs(n)} h[s]
// ---------------------------------------------------------------------------
__global__ void __launch_bounds__(256) gather_agg(const float* __restrict__ h) {
    int gw = (blockIdx.x * 256 + threadIdx.x) >> 5;
    int lane = threadIdx.x & 31;
    const float4* hv = (const float4*)h;
    float4 acc = hv[(size_t)gw * 32 + lane];
    int beg = g_off[gw];
    int end = g_off[gw + 1];
    #pragma unroll 4
    for (int j = beg; j < end; j++) {
        int s = __ldg(&g_col[j]);
        float4 v = hv[(size_t)s * 32 + lane];
        acc.x += v.x; acc.y += v.y; acc.z += v.z; acc.w += v.w;
    }
    ((float4*)g_agg)[(size_t)gw * 32 + lane] = acc;
}

// ---------------------------------------------------------------------------
// Fused 2-layer MLP on mma.sync bf16x3 (D = Ah*Wh + Ah*Wl + Al*Wh, fp32 acc).
// 8 warps/CTA, warp = 16 rows. C-frag layout == A-frag layout, so GEMM1 acc
// converts to GEMM2 A-fragments entirely in registers. No smem.
// ---------------------------------------------------------------------------
__global__ void __launch_bounds__(256, 1) mlp_mma(
    const float* __restrict__ in, float* __restrict__ outp,
    const uint4* __restrict__ bf1, const uint4* __restrict__ bf2,
    const float* __restrict__ b1g, const float* __restrict__ b2g, int nrows)
{
    const int tid = threadIdx.x;
    const int warp = tid >> 5, lane = tid & 31;
    const int g = lane >> 2, tg = lane & 3;
    const int row0 = blockIdx.x * 128 + warp * 16;
    const int r0 = row0 + g, r1 = row0 + g + 8;
    const bool v0 = r0 < nrows, v1 = r1 < nrows;

    float acc[16][4];

    // ---- GEMM1: acc = bias1; acc += A @ W1 ----
    #pragma unroll
    for (int j = 0; j < 16; ++j) {
        float2 b = *(const float2*)(b1g + j * 8 + tg * 2);
        acc[j][0] = b.x; acc[j][1] = b.y; acc[j][2] = b.x; acc[j][3] = b.y;
    }

    #pragma unroll
    for (int s = 0; s < 8; ++s) {
        int k0 = s * 16 + tg * 2;
        float2 z = make_float2(0.f, 0.f);
        float2 x0 = v0 ? *(const float2*)(in + (size_t)r0 * HID + k0)     : z;
        float2 x1 = v1 ? *(const float2*)(in + (size_t)r1 * HID + k0)     : z;
        float2 x2 = v0 ? *(const float2*)(in + (size_t)r0 * HID + k0 + 8) : z;
        float2 x3 = v1 ? *(const float2*)(in + (size_t)r1 * HID + k0 + 8) : z;
        uint32_t ah[4], al[4];
        split2(x0.x, x0.y, ah[0], al[0]);
        split2(x1.x, x1.y, ah[1], al[1]);
        split2(x2.x, x2.y, ah[2], al[2]);
        split2(x3.x, x3.y, ah[3], al[3]);
        #pragma unroll
        for (int j = 0; j < 16; ++j) {
            uint4 b = __ldg(&bf1[(j * 8 + s) * 32 + lane]);
            MMA_BF16(acc[j], ah, b.x, b.y);   // Ah*Wh
            MMA_BF16(acc[j], ah, b.z, b.w);   // Ah*Wl
            MMA_BF16(acc[j], al, b.x, b.y);   // Al*Wh
        }
    }

    // ---- epilogue1: relu -> split -> GEMM2 A fragments (pure registers) ----
    uint32_t a2h[8][4], a2l[8][4];
    #pragma unroll
    for (int jt = 0; jt < 8; ++jt) {
        float p0 = fmaxf(acc[2*jt][0], 0.f),   p1 = fmaxf(acc[2*jt][1], 0.f);
        float p2 = fmaxf(acc[2*jt][2], 0.f),   p3 = fmaxf(acc[2*jt][3], 0.f);
        float q0 = fmaxf(acc[2*jt+1][0], 0.f), q1 = fmaxf(acc[2*jt+1][1], 0.f);
        float q2 = fmaxf(acc[2*jt+1][2], 0.f), q3 = fmaxf(acc[2*jt+1][3], 0.f);
        split2(p0, p1, a2h[jt][0], a2l[jt][0]);   // row g,   k lo-half
        split2(p2, p3, a2h[jt][1], a2l[jt][1]);   // row g+8, k lo-half
        split2(q0, q1, a2h[jt][2], a2l[jt][2]);   // row g,   k hi-half
        split2(q2, q3, a2h[jt][3], a2l[jt][3]);   // row g+8, k hi-half
    }

    // ---- GEMM2: acc = bias2; acc += mid @ W2 ----
    #pragma unroll
    for (int j = 0; j < 16; ++j) {
        float2 b = *(const float2*)(b2g + j * 8 + tg * 2);
        acc[j][0] = b.x; acc[j][1] = b.y; acc[j][2] = b.x; acc[j][3] = b.y;
    }
    #pragma unroll
    for (int s = 0; s < 8; ++s) {
        #pragma unroll
        for (int j = 0; j < 16; ++j) {
            uint4 b = __ldg(&bf2[(j * 8 + s) * 32 + lane]);
            MMA_BF16(acc[j], a2h[s], b.x, b.y);
            MMA_BF16(acc[j], a2h[s], b.z, b.w);
            MMA_BF16(acc[j], a2l[s], b.x, b.y);
        }
    }

    // ---- store: relu, float2 per (row, n-tile) ----
    #pragma unroll
    for (int j = 0; j < 16; ++j) {
        int c = j * 8 + tg * 2;
        if (v0) {
            float2 w = make_float2(fmaxf(acc[j][0], 0.f), fmaxf(acc[j][1], 0.f));
            *(float2*)(outp + (size_t)r0 * HID + c) = w;
        }
        if (v1) {
            float2 w = make_float2(fmaxf(acc[j][2], 0.f), fmaxf(acc[j][3], 0.f));
            *(float2*)(outp + (size_t)r1 * HID + c) = w;
        }
    }
}

// ---------------------------------------------------------------------------
__global__ void __launch_bounds__(256) zero_pool() {
    int i = blockIdx.x * 256 + threadIdx.x;
    g_pool[i] = 0.f;
}

__global__ void __launch_bounds__(128) pool_sum(
    const float* __restrict__ h, const int* __restrict__ batch)
{
    const int CHUNK = 256;
    int col = threadIdx.x;
    int n0 = blockIdx.x * CHUNK;
    int n1 = n0 + CHUNK; if (n1 > N_NODES) n1 = N_NODES;
    if (n0 >= N_NODES) return;

    int cur = batch[n0];
    float acc = 0.f;
    for (int n = n0; n < n1; n++) {
        int b = batch[n];
        if (b != cur) {
            atomicAdd(&g_pool[(size_t)cur * HID + col], acc);
            acc = 0.f;
            cur = b;
        }
        acc += h[(size_t)n * HID + col];
    }
    atomicAdd(&g_pool[(size_t)cur * HID + col], acc);
}

__global__ void __launch_bounds__(128) heads(
    const float* __restrict__ Wmu, const float* __restrict__ bmu,
    const float* __restrict__ Wlv, const float* __restrict__ blv,
    float* __restrict__ out)
{
    __shared__ float sg[HID];
    int gi = blockIdx.x;
    sg[threadIdx.x] = g_pool[(size_t)gi * HID + threadIdx.x];
    __syncthreads();

    int t = threadIdx.x;
    const float* W = (t < LAT) ? Wmu : Wlv;
    const float* b = (t < LAT) ? bmu : blv;
    int c = t & (LAT - 1);
    float acc = b[c];
    #pragma unroll 8
    for (int k = 0; k < HID; k++) acc += sg[k] * W[k * LAT + c];

    float* o = (t < LAT) ? out : (out + (size_t)N_GRAPHS * LAT);
    o[(size_t)gi * LAT + c] = acc;
}

// ---------------------------------------------------------------------------

extern "C" void kernel_launch(void* const* d_in, const int* in_sizes, int n_in,
                              void* d_out, int out_size) {
    const float* x     = (const float*)d_in[0];
    const int*   ei    = (const int*)d_in[1];
    const int*   batch = (const int*)d_in[2];
    const float* W1    = (const float*)d_in[3];
    const float* b1    = (const float*)d_in[4];
    const float* W2    = (const float*)d_in[5];
    const float* b2    = (const float*)d_in[6];
    const float* Wmu   = (const float*)d_in[7];
    const float* bmu   = (const float*)d_in[8];
    const float* Wlv   = (const float*)d_in[9];
    const float* blv   = (const float*)d_in[10];
    float*       out   = (float*)d_out;

    const int* src = ei;
    const int* dst = ei + N_EDGES;

    float* h_ptr;   cudaGetSymbolAddress((void**)&h_ptr, g_h);
    float* agg_ptr; cudaGetSymbolAddress((void**)&agg_ptr, g_agg);
    uint4* bf_ptr;  cudaGetSymbolAddress((void**)&bf_ptr, g_bfrag);

    // ---- CSR build (once per launch) ----
    csr_zero<<<(N_NODES + 255) / 256, 256>>>();
    csr_hist<<<N_EDGES / 256, 256>>>(dst);
    scan_partial<<<SCAN_NB, SCAN_BLK>>>();
    scan_single<<<1, 32>>>();
    scan_final<<<SCAN_NB, SCAN_BLK>>>();
    csr_fill<<<N_EDGES / 256, 256>>>(src, dst);

    // ---- weight fragment precompute (once per launch) ----
    split_wfrag<<<96, 256>>>(W1, W2);

    const float* cur = x;
    for (int l = 0; l < N_LAYERS; l++) {
        gather_agg<<<(N_NODES * 32) / 256, 256>>>(cur);
        const uint4* bf1 = bf_ptr + (size_t)(l * 2 + 0) * 4096;
        const uint4* bf2 = bf_ptr + (size_t)(l * 2 + 1) * 4096;
        mlp_mma<<<TILES, 256>>>(agg_ptr, h_ptr, bf1, bf2,
                                b1 + (size_t)l * HID, b2 + (size_t)l * HID, N_NODES);
        cur = h_ptr;
    }

    zero_pool<<<(N_GRAPHS * HID) / 256, 256>>>();
    pool_sum<<<(N_NODES + 255) / 256, 128>>>(cur, batch);
    heads<<<N_GRAPHS, 128>>>(Wmu, bmu, Wlv, blv, out);
}